// round 4
// baseline (speedup 1.0000x reference)
#include <cuda_runtime.h>
#include <cstdint>
#include <cstddef>

// ---------------------------------------------------------------------------
// QAOA diff quantum simulator, N=18 qubits, B=8, 4 layers.
// R4: ONE persistent kernel (grid=256, 2 CTAs/SM guaranteed co-resident),
//     hand-rolled grid barrier between the 5 state passes; hp table generation
//     fused as phase 0 (and reused in registers for pass 1's phase);
//     13-bit chunks / 2 smem exchanges per pass (best shape, from R1/R2);
//     butterflies split lo/hi half to overlap LDG latency with compute.
// ---------------------------------------------------------------------------

namespace {
constexpr int NQ   = 18;
constexpr int QDIM = 1 << NQ;            // 262144
constexpr int NB   = 8;
constexpr int NL   = 4;
constexpr int TPB  = 256;
constexpr int RPT  = 32;                 // 5 reg bits
constexpr int CHUNK = TPB * RPT;         // 8192 (13 bits)
constexpr int CPB  = QDIM / CHUNK;       // 32
constexpr int BLOCKS = NB * CPB;         // 256
constexpr size_t SMEM_BYTES = (size_t)CHUNK * sizeof(float2); // 64 KB
}

__device__ __align__(256) float2 g_state[(size_t)NB * QDIM]; // 16 MB
__device__ __align__(16) unsigned char g_hp[(size_t)NB * QDIM]; // 2 MB
__device__ float g_partial[BLOCKS];
__device__ unsigned g_cnt = 0;
__device__ unsigned g_gen = 0;

// --------------------------- grid barrier ----------------------------------

__device__ __forceinline__ void gbar() {
  __syncthreads();
  if (threadIdx.x == 0) {
    unsigned gen = *(volatile unsigned*)&g_gen;
    __threadfence();
    if (atomicAdd(&g_cnt, 1u) == BLOCKS - 1) {
      g_cnt = 0;
      __threadfence();
      atomicAdd(&g_gen, 1u);
    } else {
      while (*(volatile unsigned*)&g_gen == gen) { }
      __threadfence();
    }
  }
  __syncthreads();
}

// --------------------------- mappings ---------------------------------------

__device__ __forceinline__ int swz(int i) { return i ^ ((i >> 5) & 31); }

template<bool G>
__device__ __forceinline__ int dmap(int cb, int local) {
  if (G)  // B: local 8..12 -> g13..17, cb -> g8..12
    return ((local >> 8) << 13) | (cb << 8) | (local & 255);
  else    // A: cb -> g13..17
    return (cb << 13) | local;
}

__device__ __forceinline__ int locM0(int tid, int r) { return (tid << 5) | r; }
__device__ __forceinline__ int locM1(int tid, int r) { return ((tid >> 5) << 10) | (r << 5) | (tid & 31); }
__device__ __forceinline__ int locM2(int tid, int r) { return (r << 8) | tid; }

// --------------------------- butterflies ------------------------------------

__device__ __forceinline__ void rotp(float2& x, float2& y, float c, float s) {
  float nx0 = fmaf(c, x.x,  s * y.y);
  float nx1 = fmaf(c, x.y, -s * y.x);
  float ny0 = fmaf(c, y.x,  s * x.y);
  float ny1 = fmaf(c, y.y, -s * x.x);
  x = make_float2(nx0, nx1);
  y = make_float2(ny0, ny1);
}

// bit P (P<4) over 16 contiguous regs
template<int P>
__device__ __forceinline__ void btf16(float2* a, float c, float s) {
#pragma unroll
  for (int h = 0; h < 8; h++) {
    int i0 = ((h >> P) << (P + 1)) | (h & ((1 << P) - 1));
    rotp(a[i0], a[i0 | (1 << P)], c, s);
  }
}
__device__ __forceinline__ void btf_lo4(float2* a, float c, float s) {
  btf16<0>(a, c, s); btf16<1>(a, c, s); btf16<2>(a, c, s); btf16<3>(a, c, s);
}
__device__ __forceinline__ void bit4(float2* a, float c, float s) {
#pragma unroll
  for (int r = 0; r < 16; r++) rotp(a[r], a[r + 16], c, s);
}
// all 5 reg bits, half-split so lo-half compute overlaps hi-half loads
__device__ __forceinline__ void btf5(float2* a, float c, float s) {
  btf_lo4(a, c, s); btf_lo4(a + 16, c, s); bit4(a, c, s);
}
// reg bits 0..2 only
__device__ __forceinline__ void btf3lo(float2* a, float c, float s) {
  btf16<0>(a, c, s); btf16<1>(a, c, s); btf16<2>(a, c, s);
  btf16<0>(a + 16, c, s); btf16<1>(a + 16, c, s); btf16<2>(a + 16, c, s);
}
// reg bits 2..4 only
__device__ __forceinline__ void btf3hi(float2* a, float c, float s) {
  btf16<2>(a, c, s); btf16<3>(a, c, s);
  btf16<2>(a + 16, c, s); btf16<3>(a + 16, c, s);
  bit4(a, c, s);
}

// --------------------------- phase apply -------------------------------------

__device__ __forceinline__ void ph_apply(float2& v, float2 ph) {
  v = make_float2(fmaf(v.x, ph.x,  v.y * ph.y),
                  fmaf(v.y, ph.x, -v.x * ph.y));
}

// --------------------------- down pass ---------------------------------------

template<bool G>
__device__ __forceinline__ void down_pass(
    float2* sh, const float2* ph_tab, const unsigned char* hpb, float2* stb,
    int cb, int tid, float cp, float sp, float cm, float sm) {
  float2 a[RPT];
#pragma unroll
  for (int r = 0; r < RPT; r++)
    a[r] = stb[dmap<G>(cb, locM2(tid, r))];
  // finish previous layer on local bits 8..12
  btf5(a, cp, sp);
  // diagonal phase
#pragma unroll
  for (int r = 0; r < RPT; r++) {
    int k = hpb[dmap<G>(cb, locM2(tid, r))];
    ph_apply(a[r], ph_tab[k]);
  }
  // main layer bits 8..12
  btf5(a, cm, sm);
  // exchange M2 -> M1
#pragma unroll
  for (int r = 0; r < RPT; r++) sh[swz(locM2(tid, r))] = a[r];
  __syncthreads();
#pragma unroll
  for (int r = 0; r < RPT; r++) a[r] = sh[swz(locM1(tid, r))];
  // main bits 5..7 (r-bits 0..2; 8,9 already done)
  btf3lo(a, cm, sm);
  // exchange M1 -> M0 (store is per-thread RMW: no sync before store)
#pragma unroll
  for (int r = 0; r < RPT; r++) sh[swz(locM1(tid, r))] = a[r];
  __syncthreads();
#pragma unroll
  for (int r = 0; r < RPT; r++) a[r] = sh[swz(locM0(tid, r))];
  // main bits 0..4
  btf5(a, cm, sm);
  // contiguous vectorized store (32 consecutive amps per thread)
  float4* dst = reinterpret_cast<float4*>(stb + dmap<G>(cb, tid << 5));
#pragma unroll
  for (int i = 0; i < RPT / 2; i++)
    dst[i] = make_float4(a[2 * i].x, a[2 * i].y, a[2 * i + 1].x, a[2 * i + 1].y);
}

// --------------------------- the one kernel ----------------------------------

__global__ void __launch_bounds__(TPB, 2)
qaoa_fused(const float* __restrict__ betas, const float* __restrict__ adj,
           float* __restrict__ out) {
  extern __shared__ float2 sh[];
  __shared__ float2 ph_tab[256];
  __shared__ int s_rm[NQ];
  __shared__ int s_sk[NQ];
  __shared__ float s_red[TPB / 32];

  const int tid = threadIdx.x;
  const int blk = blockIdx.x;
  const int b  = blk >> 5;
  const int cb = blk & 31;

  // one-time setup: phase table, edge masks, per-layer sincos
  { float sv, cv; sincosf((float)tid, &sv, &cv); ph_tab[tid] = make_float2(cv, sv); }
  if (tid < NQ) {
    int m = 0;
    const float* row = adj + (size_t)b * NQ * NQ + tid * NQ;
    for (int v = tid + 1; v < NQ; v++)
      if (row[v] > 0.5f) m |= 1 << (17 - v);
    s_rm[tid] = m;
    s_sk[tid] = __popc(m);
  }
  float cs[NL], sn[NL];
#pragma unroll
  for (int t = 0; t < NL; t++) sincosf(betas[b * NL + t], &sn[t], &cs[t]);
  __syncthreads();

  const unsigned char* hpb = g_hp + (size_t)b * QDIM;
  float2* stb = g_state + (size_t)b * QDIM;

  // ---- phase 0: hp (cut count) for this block's linear slice ----
  // d = dbase + j, j in [0,32); dbase low 5 bits are zero.
  const int dbase = (cb << 13) | (tid << 5);
  unsigned int w[8];
  {
    int ne = 0;
#pragma unroll
    for (int u = 0; u < NQ; u++) ne += s_sk[u];
    int cr[32];
#pragma unroll
    for (int j = 0; j < 32; j++) cr[j] = 0;
#pragma unroll
    for (int u = 0; u < NQ; u++) {
      const int m = s_rm[u];
      const int kk = s_sk[u] - 2 * __popc(dbase & m);
      const int mlow = m & 31;
      if (u < 13) {  // sign bit (17-u) >= 5: constant over j
        const int sgn = (dbase >> (17 - u)) & 1;
#pragma unroll
        for (int j = 0; j < 32; j++) {
          int t2 = kk - 2 * __popc(j & mlow);
          cr[j] += sgn ? -t2 : t2;
        }
      } else {       // sign bit in j
        const int sb = 17 - u;
#pragma unroll
        for (int j = 0; j < 32; j++) {
          int t2 = kk - 2 * __popc(j & mlow);
          cr[j] += ((j >> sb) & 1) ? -t2 : t2;
        }
      }
    }
#pragma unroll
    for (int q = 0; q < 8; q++) {
      unsigned int p = 0;
#pragma unroll
      for (int e = 0; e < 4; e++)
        p |= (unsigned int)((ne - cr[q * 4 + e]) >> 1) << (e * 8);
      w[q] = p;
    }
    uint4* hdst = reinterpret_cast<uint4*>(const_cast<unsigned char*>(hpb) + dbase);
    hdst[0] = make_uint4(w[0], w[1], w[2], w[3]);
    hdst[1] = make_uint4(w[4], w[5], w[6], w[7]);
  }

  // ---- P1 (layout A, up): init + phi + RX_1 on local bits 0..12 ----
  {
    float2 a[RPT];
    const float inv = 0.001953125f;  // 1/sqrt(2^18)
#pragma unroll
    for (int r = 0; r < RPT; r++) {
      int k = (w[r >> 2] >> ((r & 3) << 3)) & 0xFF;
      float2 ph = ph_tab[k];
      a[r] = make_float2(inv * ph.x, -inv * ph.y);
    }
    btf5(a, cs[0], sn[0]);                       // bits 0..4
#pragma unroll
    for (int r = 0; r < RPT; r++) sh[swz(locM0(tid, r))] = a[r];
    __syncthreads();
#pragma unroll
    for (int r = 0; r < RPT; r++) a[r] = sh[swz(locM1(tid, r))];
    btf5(a, cs[0], sn[0]);                       // bits 5..9
#pragma unroll
    for (int r = 0; r < RPT; r++) sh[swz(locM1(tid, r))] = a[r];  // RMW
    __syncthreads();
#pragma unroll
    for (int r = 0; r < RPT; r++) a[r] = sh[swz(locM2(tid, r))];
    btf3hi(a, cs[0], sn[0]);                     // bits 10..12 (8,9 done)
#pragma unroll
    for (int r = 0; r < RPT; r++)
      stb[dmap<false>(cb, locM2(tid, r))] = a[r];
  }
  gbar();

  // ---- P2 (B): RX1 g13..17 + phi + RX2 ----
  down_pass<true >(sh, ph_tab, hpb, stb, cb, tid, cs[0], sn[0], cs[1], sn[1]);
  gbar();
  // ---- P3 (A): RX2 g8..12 + phi + RX3 ----
  down_pass<false>(sh, ph_tab, hpb, stb, cb, tid, cs[1], sn[1], cs[2], sn[2]);
  gbar();
  // ---- P4 (B): RX3 g13..17 + phi + RX4 ----
  down_pass<true >(sh, ph_tab, hpb, stb, cb, tid, cs[2], sn[2], cs[3], sn[3]);
  gbar();

  // ---- P5 (A): RX4 g8..12 + energy ----
  {
    float2 a[RPT];
#pragma unroll
    for (int r = 0; r < RPT; r++)
      a[r] = stb[dmap<false>(cb, locM2(tid, r))];
    btf5(a, cs[3], sn[3]);
    float e = 0.f;
#pragma unroll
    for (int r = 0; r < RPT; r++) {
      int k = hpb[dmap<false>(cb, locM2(tid, r))];
      e += (a[r].x * a[r].x + a[r].y * a[r].y) * (float)k;
    }
#pragma unroll
    for (int o = 16; o; o >>= 1) e += __shfl_down_sync(0xffffffffu, e, o);
    if ((tid & 31) == 0) s_red[tid >> 5] = e;
    __syncthreads();
    if (tid == 0) {
      float t = 0.f;
#pragma unroll
      for (int i = 0; i < TPB / 32; i++) t += s_red[i];
      g_partial[blk] = t;
    }
  }
  gbar();

  // ---- final reduce: one block per batch ----
  if (cb == 0 && tid < 32) {
    float t = g_partial[b * CPB + tid];
#pragma unroll
    for (int o = 16; o; o >>= 1) t += __shfl_down_sync(0xffffffffu, t, o);
    if (tid == 0) out[b] = t;
  }
}

// --------------------------- launch ----------------------------------------

extern "C" void kernel_launch(void* const* d_in, const int* in_sizes, int n_in,
                              void* d_out, int out_size) {
  const float* betas = (const float*)d_in[0];
  const float* adj   = (const float*)d_in[1];
  if (n_in >= 2 && in_sizes[0] != NB * NL) {
    betas = (const float*)d_in[1];
    adj   = (const float*)d_in[0];
  }
  float* out = (float*)d_out;
  (void)out_size;

  cudaFuncSetAttribute(qaoa_fused, cudaFuncAttributeMaxDynamicSharedMemorySize,
                       (int)SMEM_BYTES);
  qaoa_fused<<<BLOCKS, TPB, SMEM_BYTES>>>(betas, adj, out);
}

// round 5
// speedup vs baseline: 1.1730x; 1.1730x over previous
#include <cuda_runtime.h>
#include <cstdint>
#include <cstddef>

// ---------------------------------------------------------------------------
// QAOA diff quantum simulator, N=18 qubits, B=8, 4 layers.
// R5: R2 multi-kernel structure + packed f32x2 math (FFMA2/FMUL2).
//
// State storage: one 16B "element" per pair of amplitudes differing in amp
// bit 0:  float4 {re(2e), re(2e+1), im(2e), im(2e+1)}.  Butterflies on bits
// >=1 act identically on both lanes -> pure SIMD (4 packed ops per element
// pair vs 8 scalar per amp pair).  Bit 0 = intra-element swap variant.
//
// Element space per batch: 17 bits (amp bits 1..17 -> element bits 0..16).
// Per pass: local L = 12 block bits (tid 8 + r 4), cb = 5 chunk bits.
//   Layout A: e = (cb<<12)|L            L0..11 = amp1..12, cb = amp13..17
//   Layout B: e = ((L>>7)<<12)|(cb<<7)|(L&127)
//             L0..6 = amp1..7, L7..11 = amp13..17, cb = amp8..12
// Residencies: M0: r=L0..3, M1: r=L4..7, M2: r=L8..11 (disjoint).
// Down pass: M2[pre L8..11] -> M1[pre L7, phi, main L4..7]
//            -> M2[main L8..11] -> M0[main L0..3 + lane].
// Pre = 5 leftover bits of prev layer: A: amp8..12 = L7..11; B: amp13..17 =
// L7..11.  Main covers lane + L0..11 = 13 bits.  5 passes as before.
// ---------------------------------------------------------------------------

namespace {
constexpr int NQ   = 18;
constexpr int QDIM = 1 << NQ;             // 262144 amps
constexpr int EDIM = QDIM / 2;            // 131072 elements
constexpr int NB   = 8;
constexpr int NL   = 4;
constexpr int TPB  = 256;
constexpr int EPT  = 16;                  // elements per thread (r = 4 bits)
constexpr int CHUNKE = TPB * EPT;         // 4096 elements per block
constexpr int CPB  = EDIM / CHUNKE;       // 32
constexpr int BLOCKS = NB * CPB;          // 256
constexpr size_t SMEM_BYTES = (size_t)CHUNKE * 16; // 64 KB
}

__device__ __align__(256) float4 g_state[(size_t)NB * EDIM]; // 16 MB
__device__ __align__(16) unsigned char g_hp[(size_t)NB * QDIM]; // 2 MB
__device__ float g_partial[BLOCKS];

// --------------------------- packed f32x2 helpers ---------------------------

using u64 = unsigned long long;

__device__ __forceinline__ u64 pk2(float lo, float hi) {
  u64 d; asm("mov.b64 %0, {%1, %2};" : "=l"(d) : "f"(lo), "f"(hi)); return d;
}
__device__ __forceinline__ void upk2(float& lo, float& hi, u64 v) {
  asm("mov.b64 {%0, %1}, %2;" : "=f"(lo), "=f"(hi) : "l"(v));
}
__device__ __forceinline__ u64 mul2(u64 a, u64 b) {
  u64 d; asm("mul.rn.f32x2 %0, %1, %2;" : "=l"(d) : "l"(a), "l"(b)); return d;
}
__device__ __forceinline__ u64 fma2(u64 a, u64 b, u64 c) {
  u64 d; asm("fma.rn.f32x2 %0, %1, %2, %3;" : "=l"(d) : "l"(a), "l"(b), "l"(c));
  return d;
}
__device__ __forceinline__ u64 swp2(u64 v) {
  float lo, hi; upk2(lo, hi, v); return pk2(hi, lo);
}

struct El { u64 re, im; };

// RX butterfly on an element PAIR (amp bit >= 1): 8 packed-pipe ops / 4 amps.
// scalar ref: nx.re = c*x.re + s*y.im ; nx.im = c*x.im - s*y.re (and x<->y)
__device__ __forceinline__ void rot2(El& x, El& y, u64 cc, u64 ss, u64 ns) {
  u64 t1 = mul2(ss, y.im);
  u64 t2 = mul2(ns, y.re);
  u64 t3 = mul2(ss, x.im);
  u64 t4 = mul2(ns, x.re);
  x.re = fma2(cc, x.re, t1);
  x.im = fma2(cc, x.im, t2);
  y.re = fma2(cc, y.re, t3);
  y.im = fma2(cc, y.im, t4);
}

// RX butterfly on amp bit 0 (intra-element): swap lanes of the partner.
__device__ __forceinline__ void rot2_lane(El& x, u64 cc, u64 ss, u64 ns) {
  u64 sre = swp2(x.re), sim = swp2(x.im);
  x.re = fma2(cc, x.re, mul2(ss, sim));
  x.im = fma2(cc, x.im, mul2(ns, sre));
}

// butterfly over r-bit P on 16 resident elements
template<int P>
__device__ __forceinline__ void btfE(El* a, u64 cc, u64 ss, u64 ns) {
#pragma unroll
  for (int h = 0; h < EPT / 2; h++) {
    int i0 = ((h >> P) << (P + 1)) | (h & ((1 << P) - 1));
    rot2(a[i0], a[i0 | (1 << P)], cc, ss, ns);
  }
}
__device__ __forceinline__ void btfE4(El* a, u64 cc, u64 ss, u64 ns) {
  btfE<0>(a, cc, ss, ns); btfE<1>(a, cc, ss, ns);
  btfE<2>(a, cc, ss, ns); btfE<3>(a, cc, ss, ns);
}

// diagonal phase on one element: k0,k1 = hp bytes; multiply by exp(-i k)
__device__ __forceinline__ void ph2(El& x, const float2* tab, int k0, int k1) {
  float2 p0 = tab[k0], p1 = tab[k1];
  u64 C  = pk2(p0.x, p1.x);
  u64 S  = pk2(p0.y, p1.y);
  u64 nS = pk2(-p0.y, -p1.y);
  u64 t = mul2(S, x.im);
  u64 u = mul2(nS, x.re);
  x.re = fma2(C, x.re, t);
  x.im = fma2(C, x.im, u);
}

// --------------------------- mappings ---------------------------------------

__device__ __forceinline__ int swz16(int s) { return s ^ ((s >> 4) & 15); }

template<bool G>
__device__ __forceinline__ int dmap(int cb, int L) {
  if (G)  // B
    return ((L >> 7) << 12) | (cb << 7) | (L & 127);
  else    // A
    return (cb << 12) | L;
}
__device__ __forceinline__ int locM0(int tid, int r) { return (tid << 4) | r; }
__device__ __forceinline__ int locM1(int tid, int r) { return ((tid >> 4) << 8) | (r << 4) | (tid & 15); }
__device__ __forceinline__ int locM2(int tid, int r) { return (r << 8) | tid; }

// --------------------------- hp (cut-count) kernel --------------------------

__global__ void hp_kernel(const float* __restrict__ adj) {
  __shared__ int rm[NQ];
  __shared__ int sk[NQ];
  __shared__ int sne;
  const int b = blockIdx.x >> 7;
  const int dbase = (blockIdx.x & 127) << 11;
  const int tid = threadIdx.x;

  if (tid < NQ) {
    int m = 0;
    const float* row = adj + (size_t)b * NQ * NQ + tid * NQ;
    for (int v = tid + 1; v < NQ; v++)
      if (row[v] > 0.5f) m |= 1 << (17 - v);
    rm[tid] = m;
    sk[tid] = __popc(m);
  }
  __syncthreads();
  if (tid == 0) {
    int ne = 0;
    for (int u = 0; u < NQ; u++) ne += sk[u];
    sne = ne;
  }
  __syncthreads();
  const int ne = sne;
  unsigned char* hb = g_hp + (size_t)b * QDIM + dbase;
#pragma unroll
  for (int i = 0; i < 8; i++) {
    int d = dbase + tid + i * 256;
    int cross = 0;
#pragma unroll
    for (int u = 0; u < NQ; u++) {
      int m = rm[u];
      int t = sk[u] - 2 * __popc(d & m);
      cross += ((d >> (17 - u)) & 1) ? -t : t;
    }
    hb[tid + i * 256] = (unsigned char)((ne - cross) >> 1);
  }
}

// --------------------------- pass kernels ------------------------------------

__device__ __forceinline__ void build_tab(float2* ph_tab, int tid) {
  float sv, cv; sincosf((float)tid, &sv, &cv);
  ph_tab[tid] = make_float2(cv, sv);
}

__device__ __forceinline__ El ld_el(const float4* st4, int e) {
  float4 v = st4[e];
  El x; x.re = pk2(v.x, v.y); x.im = pk2(v.z, v.w); return x;
}
__device__ __forceinline__ void st_el(float4* st4, int e, El x) {
  float4 v;
  upk2(v.x, v.y, x.re); upk2(v.z, v.w, x.im);
  st4[e] = v;
}
__device__ __forceinline__ void sts_el(float4* sh, int s, El x) {
  float4 v; upk2(v.x, v.y, x.re); upk2(v.z, v.w, x.im);
  sh[s] = v;
}
__device__ __forceinline__ El lds_el(const float4* sh, int s) {
  float4 v = sh[s];
  El x; x.re = pk2(v.x, v.y); x.im = pk2(v.z, v.w); return x;
}

// ---- P1: layout A, init + phi + RX1 on amp 0..12 (up: M0 -> M1 -> M2) ----
__global__ void __launch_bounds__(TPB, 2)
pass_init(const float* __restrict__ betas) {
  extern __shared__ float4 sh[];
  __shared__ float2 ph_tab[256];
  const int tid = threadIdx.x;
  const int b = blockIdx.x >> 5, cb = blockIdx.x & 31;

  build_tab(ph_tab, tid);
  float cm, sm; sincosf(betas[b * NL + 0], &sm, &cm);
  const u64 cc = pk2(cm, cm), ss = pk2(sm, sm), ns = pk2(-sm, -sm);
  __syncthreads();

  const unsigned char* hpb = g_hp + (size_t)b * QDIM;
  float4* st4 = g_state + (size_t)b * EDIM;

  El a[EPT];
  // init + phase: M0 elements contiguous -> 32 contiguous hp bytes / thread
  {
    const float inv = 0.001953125f;  // 1/sqrt(2^18)
    const int e0 = dmap<false>(cb, tid << 4);
    const uint2* hv = reinterpret_cast<const uint2*>(hpb + 2 * (size_t)e0);
    uint2 h0 = hv[0], h1 = hv[1], h2 = hv[2], h3 = hv[3];
    unsigned int w[8] = {h0.x, h0.y, h1.x, h1.y, h2.x, h2.y, h3.x, h3.y};
#pragma unroll
    for (int r = 0; r < EPT; r++) {
      int k0 = (w[r >> 1] >> ((r & 1) << 4)) & 0xFF;
      int k1 = (w[r >> 1] >> (((r & 1) << 4) + 8)) & 0xFF;
      float2 p0 = ph_tab[k0], p1 = ph_tab[k1];
      a[r].re = pk2(inv * p0.x, inv * p1.x);
      a[r].im = pk2(-inv * p0.y, -inv * p1.y);
    }
  }
  btfE4(a, cc, ss, ns);                                 // L0..3 (amp1..4)
#pragma unroll
  for (int r = 0; r < EPT; r++) rot2_lane(a[r], cc, ss, ns); // amp0
#pragma unroll
  for (int r = 0; r < EPT; r++) sts_el(sh, swz16(locM0(tid, r)), a[r]);
  __syncthreads();
#pragma unroll
  for (int r = 0; r < EPT; r++) a[r] = lds_el(sh, swz16(locM1(tid, r)));
  btfE4(a, cc, ss, ns);                                 // L4..7
#pragma unroll
  for (int r = 0; r < EPT; r++) sts_el(sh, swz16(locM1(tid, r)), a[r]); // RMW
  __syncthreads();
#pragma unroll
  for (int r = 0; r < EPT; r++) a[r] = lds_el(sh, swz16(locM2(tid, r)));
  btfE4(a, cc, ss, ns);                                 // L8..11
#pragma unroll
  for (int r = 0; r < EPT; r++) st_el(st4, dmap<false>(cb, locM2(tid, r)), a[r]);
}

// ---- down pass: pre(5) + phi + main(13) ----
template<bool G>
__global__ void __launch_bounds__(TPB, 2)
pass_down(const float* __restrict__ betas, int pre_layer) {
  extern __shared__ float4 sh[];
  __shared__ float2 ph_tab[256];
  const int tid = threadIdx.x;
  const int b = blockIdx.x >> 5, cb = blockIdx.x & 31;

  build_tab(ph_tab, tid);
  float cp, sp, cm, sm;
  sincosf(betas[b * NL + pre_layer], &sp, &cp);
  sincosf(betas[b * NL + pre_layer + 1], &sm, &cm);
  const u64 ccp = pk2(cp, cp), ssp = pk2(sp, sp), nsp = pk2(-sp, -sp);
  const u64 ccm = pk2(cm, cm), ssm = pk2(sm, sm), nsm = pk2(-sm, -sm);

  const unsigned char* hpb = g_hp + (size_t)b * QDIM;
  float4* st4 = g_state + (size_t)b * EDIM;

  El a[EPT];
#pragma unroll
  for (int r = 0; r < EPT; r++)
    a[r] = ld_el(st4, dmap<G>(cb, locM2(tid, r)));
  btfE4(a, ccp, ssp, nsp);                              // pre L8..11
#pragma unroll
  for (int r = 0; r < EPT; r++) sts_el(sh, swz16(locM2(tid, r)), a[r]);
  __syncthreads();                                      // also covers ph_tab
#pragma unroll
  for (int r = 0; r < EPT; r++) a[r] = lds_el(sh, swz16(locM1(tid, r)));
  btfE<3>(a, ccp, ssp, nsp);                            // pre L7 (r-bit 3)
  // phase (hp bytes of element e are hp[2e], hp[2e+1] -> one u16)
#pragma unroll
  for (int r = 0; r < EPT; r++) {
    int e = dmap<G>(cb, locM1(tid, r));
    unsigned int h = *reinterpret_cast<const unsigned short*>(hpb + 2 * (size_t)e);
    ph2(a[r], ph_tab, h & 0xFF, h >> 8);
  }
  btfE4(a, ccm, ssm, nsm);                              // main L4..7
#pragma unroll
  for (int r = 0; r < EPT; r++) sts_el(sh, swz16(locM1(tid, r)), a[r]); // RMW
  __syncthreads();
#pragma unroll
  for (int r = 0; r < EPT; r++) a[r] = lds_el(sh, swz16(locM2(tid, r)));
  btfE4(a, ccm, ssm, nsm);                              // main L8..11
#pragma unroll
  for (int r = 0; r < EPT; r++) sts_el(sh, swz16(locM2(tid, r)), a[r]); // RMW
  __syncthreads();
#pragma unroll
  for (int r = 0; r < EPT; r++) a[r] = lds_el(sh, swz16(locM0(tid, r)));
  btfE4(a, ccm, ssm, nsm);                              // main L0..3
#pragma unroll
  for (int r = 0; r < EPT; r++) rot2_lane(a[r], ccm, ssm, nsm); // amp0
  // M0 contiguous store
  const int e0 = dmap<G>(cb, tid << 4);
#pragma unroll
  for (int r = 0; r < EPT; r++) st_el(st4, e0 + r, a[r]);
}

// ---- P5: layout A, pre RX4 (amp8..12) + energy ----
__global__ void __launch_bounds__(TPB, 2)
pass_energy(const float* __restrict__ betas) {
  extern __shared__ float4 sh[];
  __shared__ float red[TPB / 32];
  const int tid = threadIdx.x;
  const int b = blockIdx.x >> 5, cb = blockIdx.x & 31;

  float cp, sp; sincosf(betas[b * NL + 3], &sp, &cp);
  const u64 ccp = pk2(cp, cp), ssp = pk2(sp, sp), nsp = pk2(-sp, -sp);

  const unsigned char* hpb = g_hp + (size_t)b * QDIM;
  const float4* st4 = g_state + (size_t)b * EDIM;

  El a[EPT];
#pragma unroll
  for (int r = 0; r < EPT; r++)
    a[r] = ld_el(st4, dmap<false>(cb, locM2(tid, r)));
  btfE4(a, ccp, ssp, nsp);                              // pre L8..11
#pragma unroll
  for (int r = 0; r < EPT; r++) sts_el(sh, swz16(locM2(tid, r)), a[r]);
  __syncthreads();
#pragma unroll
  for (int r = 0; r < EPT; r++) a[r] = lds_el(sh, swz16(locM1(tid, r)));
  btfE<3>(a, ccp, ssp, nsp);                            // pre L7

  float e = 0.f;
#pragma unroll
  for (int r = 0; r < EPT; r++) {
    int el = dmap<false>(cb, locM1(tid, r));
    unsigned int h = *reinterpret_cast<const unsigned short*>(hpb + 2 * (size_t)el);
    u64 p2 = fma2(a[r].im, a[r].im, mul2(a[r].re, a[r].re));
    float p0, p1; upk2(p0, p1, p2);
    e = fmaf(p0, (float)(h & 0xFF), e);
    e = fmaf(p1, (float)(h >> 8), e);
  }
#pragma unroll
  for (int o = 16; o; o >>= 1) e += __shfl_down_sync(0xffffffffu, e, o);
  if ((tid & 31) == 0) red[tid >> 5] = e;
  __syncthreads();
  if (tid == 0) {
    float t = 0.f;
#pragma unroll
    for (int i = 0; i < TPB / 32; i++) t += red[i];
    g_partial[blockIdx.x] = t;
  }
}

__global__ void k_finish(float* __restrict__ out) {
  int b = threadIdx.x;
  if (b < NB) {
    float t = 0.f;
#pragma unroll
    for (int i = 0; i < CPB; i++) t += g_partial[b * CPB + i];
    out[b] = t;
  }
}

// --------------------------- launch ----------------------------------------

extern "C" void kernel_launch(void* const* d_in, const int* in_sizes, int n_in,
                              void* d_out, int out_size) {
  const float* betas = (const float*)d_in[0];
  const float* adj   = (const float*)d_in[1];
  if (n_in >= 2 && in_sizes[0] != NB * NL) {
    betas = (const float*)d_in[1];
    adj   = (const float*)d_in[0];
  }
  float* out = (float*)d_out;
  (void)out_size;

  cudaFuncSetAttribute(pass_init,       cudaFuncAttributeMaxDynamicSharedMemorySize, (int)SMEM_BYTES);
  cudaFuncSetAttribute(pass_down<true>, cudaFuncAttributeMaxDynamicSharedMemorySize, (int)SMEM_BYTES);
  cudaFuncSetAttribute(pass_down<false>,cudaFuncAttributeMaxDynamicSharedMemorySize, (int)SMEM_BYTES);
  cudaFuncSetAttribute(pass_energy,     cudaFuncAttributeMaxDynamicSharedMemorySize, (int)SMEM_BYTES);

  hp_kernel<<<NB * 128, 256>>>(adj);
  pass_init<<<BLOCKS, TPB, SMEM_BYTES>>>(betas);          // phi1 + RX1 amp0..12
  pass_down<true ><<<BLOCKS, TPB, SMEM_BYTES>>>(betas, 0);// RX1 13..17, phi, RX2
  pass_down<false><<<BLOCKS, TPB, SMEM_BYTES>>>(betas, 1);// RX2 8..12,  phi, RX3
  pass_down<true ><<<BLOCKS, TPB, SMEM_BYTES>>>(betas, 2);// RX3 13..17, phi, RX4
  pass_energy<<<BLOCKS, TPB, SMEM_BYTES>>>(betas);        // RX4 8..12 + energy
  k_finish<<<1, 32>>>(out);
}